// round 2
// baseline (speedup 1.0000x reference)
#include <cuda_runtime.h>
#include <cstdint>

// StateObsMLP: B=2048 rows, C=32 categories.
//   obs_emb  = obs(512)   @ obs_W(512x256)        + obs_b
//   state_emb= relu(state(64) @ state_W[c](64x256) + state_b[c])
//   out      = concat(state_emb, obs_emb)(512) @ l2_W[c](512x256) + l2_b[c]
//
// Strategy: bin rows by category, then one CTA per (category, 16-row tile)
// computes everything fused, streaming the category's weights once per tile.

#define CATS     32
#define SDIM     64
#define EMB      256
#define ODIM     512
#define XDIM     512
#define MT       16     // rows per tile
#define KC       32     // K-chunk for streamed weights
#define NTHREADS 256
#define B_MAX    2048

__device__ int g_perm[B_MAX];
__device__ int g_cat_start[CATS + 1];

// ---------------------------------------------------------------------------
// Kernel 1: bin rows by category (single CTA; order within a category is
// irrelevant because each row's result is independent of tile membership).
// ---------------------------------------------------------------------------
__global__ void bin_kernel(const int* __restrict__ cat, int B) {
    __shared__ int cnt[CATS];
    __shared__ int st[CATS + 1];
    __shared__ int cur[CATS];
    int t = threadIdx.x;
    if (t < CATS) cnt[t] = 0;
    __syncthreads();
    for (int b = t; b < B; b += blockDim.x) atomicAdd(&cnt[cat[b]], 1);
    __syncthreads();
    if (t == 0) {
        int s = 0;
        for (int c = 0; c < CATS; c++) { st[c] = s; s += cnt[c]; }
        st[CATS] = s;
    }
    __syncthreads();
    if (t < CATS) cur[t] = st[t];
    __syncthreads();
    for (int b = t; b < B; b += blockDim.x) {
        int pos = atomicAdd(&cur[cat[b]], 1);
        g_perm[pos] = b;
    }
    if (t <= CATS) g_cat_start[t] = st[t];
}

// ---------------------------------------------------------------------------
// Register-tiled GEMM phase: acc[4 rows][4 cols], A (row-major, smem),
// W (K x 256, global) streamed through double-buffered cp.async chunks.
// Thread t: rows r0..r0+3 (r0=(t>>6)*4), cols 4*(t&63)..+3.
// ---------------------------------------------------------------------------
__device__ __forceinline__ void gemm_tile(
    const float* __restrict__ A, int lda,
    const float* __restrict__ W, int K,
    float* w0, float* w1,
    int r0, int c64, float4 acc[4])
{
    const float4* Wv = (const float4*)W;
    int t = threadIdx.x;
    // prologue: chunk 0
    {
        uint32_t dst = (uint32_t)__cvta_generic_to_shared(w0);
        #pragma unroll
        for (int i = t; i < KC * 64; i += NTHREADS)
            asm volatile("cp.async.cg.shared.global [%0], [%1], 16;"
                         :: "r"(dst + i * 16), "l"(Wv + i));
        asm volatile("cp.async.commit_group;");
    }
    int nch = K / KC;
    for (int ch = 0; ch < nch; ch++) {
        float* wb = (ch & 1) ? w1 : w0;
        if (ch + 1 < nch) {
            float* nb = (ch & 1) ? w0 : w1;
            const float4* src = Wv + (ch + 1) * (KC * 64);
            uint32_t dst = (uint32_t)__cvta_generic_to_shared(nb);
            #pragma unroll
            for (int i = t; i < KC * 64; i += NTHREADS)
                asm volatile("cp.async.cg.shared.global [%0], [%1], 16;"
                             :: "r"(dst + i * 16), "l"(src + i));
            asm volatile("cp.async.commit_group;");
            asm volatile("cp.async.wait_group 1;");
        } else {
            asm volatile("cp.async.wait_group 0;");
        }
        __syncthreads();
        const float* A0 = A + (r0 + 0) * lda + ch * KC;
        const float* A1 = A0 + lda;
        const float* A2 = A1 + lda;
        const float* A3 = A2 + lda;
        const float4* Wrow = (const float4*)wb + c64;
        #pragma unroll 8
        for (int kk = 0; kk < KC; kk++) {
            float a0 = A0[kk], a1 = A1[kk], a2 = A2[kk], a3 = A3[kk];
            float4 w = Wrow[kk * 64];
            acc[0].x = fmaf(a0, w.x, acc[0].x);
            acc[0].y = fmaf(a0, w.y, acc[0].y);
            acc[0].z = fmaf(a0, w.z, acc[0].z);
            acc[0].w = fmaf(a0, w.w, acc[0].w);
            acc[1].x = fmaf(a1, w.x, acc[1].x);
            acc[1].y = fmaf(a1, w.y, acc[1].y);
            acc[1].z = fmaf(a1, w.z, acc[1].z);
            acc[1].w = fmaf(a1, w.w, acc[1].w);
            acc[2].x = fmaf(a2, w.x, acc[2].x);
            acc[2].y = fmaf(a2, w.y, acc[2].y);
            acc[2].z = fmaf(a2, w.z, acc[2].z);
            acc[2].w = fmaf(a2, w.w, acc[2].w);
            acc[3].x = fmaf(a3, w.x, acc[3].x);
            acc[3].y = fmaf(a3, w.y, acc[3].y);
            acc[3].z = fmaf(a3, w.z, acc[3].z);
            acc[3].w = fmaf(a3, w.w, acc[3].w);
        }
        __syncthreads();
    }
}

// ---------------------------------------------------------------------------
// Kernel 2: fused per (category, 16-row tile).
// smem layout (floats): s_s[16][64] | o_s[16][512] | x_s[16][512] | w0 | w1
// ---------------------------------------------------------------------------
#define SMEM_FLOATS (MT * SDIM + MT * ODIM + MT * XDIM + 2 * KC * EMB)

__global__ __launch_bounds__(NTHREADS, 1)
void fused_kernel(const float* __restrict__ state,
                  const float* __restrict__ obs,
                  const float* __restrict__ obs_W,
                  const float* __restrict__ obs_b,
                  const float* __restrict__ state_W,
                  const float* __restrict__ state_b,
                  const float* __restrict__ l2_W,
                  const float* __restrict__ l2_b,
                  float* __restrict__ out)
{
    extern __shared__ float sm[];
    __shared__ int rows_sh[MT];
    float* s_s = sm;                      // 16 x 64
    float* o_s = s_s + MT * SDIM;         // 16 x 512
    float* x_s = o_s + MT * ODIM;         // 16 x 512 (concat target)
    float* w0  = x_s + MT * XDIM;         // 32 x 256
    float* w1  = w0 + KC * EMB;           // 32 x 256

    int g = blockIdx.x;
    int start = g_cat_start[g];
    int cnt   = g_cat_start[g + 1] - start;
    int ntiles = (cnt + MT - 1) >> 4;

    int t   = threadIdx.x;
    int r0  = (t >> 6) << 2;   // row group base (0,4,8,12)
    int c64 = t & 63;          // float4 column index (cols 4*c64..+3)

    for (int tile = blockIdx.y; tile < ntiles; tile += gridDim.y) {
        __syncthreads();  // protect rows_sh / smem tiles from previous iter
        int base = start + tile * MT;
        if (t < MT) rows_sh[t] = (tile * MT + t < cnt) ? g_perm[base + t] : -1;
        __syncthreads();

        // --- load gathered state rows: 16x64 = 256 float4, one per thread
        {
            int r = t >> 4, c4 = t & 15;
            int row = rows_sh[r];
            float4 v = make_float4(0.f, 0.f, 0.f, 0.f);
            if (row >= 0) v = ((const float4*)state)[row * 16 + c4];
            ((float4*)s_s)[t] = v;
        }
        // --- load gathered obs rows: 16x512 = 2048 float4
        #pragma unroll
        for (int i = t; i < MT * 128; i += NTHREADS) {
            int r = i >> 7, c4 = i & 127;
            int row = rows_sh[r];
            float4 v = make_float4(0.f, 0.f, 0.f, 0.f);
            if (row >= 0) v = ((const float4*)obs)[row * 128 + c4];
            ((float4*)o_s)[i] = v;
        }
        __syncthreads();

        float4 acc[4];

        // --- Phase A: state_emb = relu(state @ state_W[g] + state_b[g])
        {
            float4 bb = ((const float4*)(state_b + g * EMB))[c64];
            acc[0] = bb; acc[1] = bb; acc[2] = bb; acc[3] = bb;
            gemm_tile(s_s, SDIM, state_W + (size_t)g * SDIM * EMB, SDIM,
                      w0, w1, r0, c64, acc);
            #pragma unroll
            for (int ri = 0; ri < 4; ri++) {
                float4 v;
                v.x = fmaxf(acc[ri].x, 0.f);
                v.y = fmaxf(acc[ri].y, 0.f);
                v.z = fmaxf(acc[ri].z, 0.f);
                v.w = fmaxf(acc[ri].w, 0.f);
                ((float4*)(x_s + (r0 + ri) * XDIM))[c64] = v;
            }
        }

        // --- Phase B: obs_emb = obs @ obs_W + obs_b  (cols 256..511 of x)
        {
            float4 bb = ((const float4*)obs_b)[c64];
            acc[0] = bb; acc[1] = bb; acc[2] = bb; acc[3] = bb;
            gemm_tile(o_s, ODIM, obs_W, ODIM, w0, w1, r0, c64, acc);
            #pragma unroll
            for (int ri = 0; ri < 4; ri++)
                ((float4*)(x_s + (r0 + ri) * XDIM + EMB))[c64] = acc[ri];
        }
        // x_s stores are ordered before the first read inside phase C's
        // chunk loop by the __syncthreads() that follows cp.async.wait there.

        // --- Phase C: out = x @ l2_W[g] + l2_b[g], scatter to original rows
        {
            float4 bb = ((const float4*)(l2_b + g * EMB))[c64];
            acc[0] = bb; acc[1] = bb; acc[2] = bb; acc[3] = bb;
            gemm_tile(x_s, XDIM, l2_W + (size_t)g * XDIM * EMB, XDIM,
                      w0, w1, r0, c64, acc);
            #pragma unroll
            for (int ri = 0; ri < 4; ri++) {
                int row = rows_sh[r0 + ri];
                if (row >= 0)
                    ((float4*)(out + (size_t)row * EMB))[c64] = acc[ri];
            }
        }
    }
}

// ---------------------------------------------------------------------------
extern "C" void kernel_launch(void* const* d_in, const int* in_sizes, int n_in,
                              void* d_out, int out_size) {
    const float* state   = (const float*)d_in[0];
    const float* obs     = (const float*)d_in[1];
    const int*   cat_ids = (const int*)  d_in[2];
    const float* obs_W   = (const float*)d_in[3];
    const float* obs_b   = (const float*)d_in[4];
    const float* state_W = (const float*)d_in[5];
    const float* state_b = (const float*)d_in[6];
    const float* l2_W    = (const float*)d_in[7];
    const float* l2_b    = (const float*)d_in[8];
    float* out = (float*)d_out;

    int B = in_sizes[2];  // cat_ids element count

    size_t smem_bytes = SMEM_FLOATS * sizeof(float);  // 135168
    cudaFuncSetAttribute(fused_kernel,
                         cudaFuncAttributeMaxDynamicSharedMemorySize,
                         (int)smem_bytes);

    bin_kernel<<<1, NTHREADS>>>(cat_ids, B);

    dim3 grid(CATS, 8);  // 256 CTAs; tile-stride loop handles any skew
    fused_kernel<<<grid, NTHREADS, smem_bytes>>>(
        state, obs, obs_W, obs_b, state_W, state_b, l2_W, l2_b, out);
}

// round 3
// speedup vs baseline: 1.0351x; 1.0351x over previous
#include <cuda_runtime.h>
#include <cstdint>

// StateObsMLP: B=2048 rows, C=32 categories.
//   obs_emb  = obs(512)   @ obs_W(512x256)        + obs_b
//   state_emb= relu(state(64) @ state_W[c](64x256) + state_b[c])
//   out      = concat(state_emb, obs_emb)(512) @ l2_W[c](512x256) + l2_b[c]
//
// R3: 512-thread CTAs with K-parity split (group0=even K-chunks, group1=odd),
// group-scoped named barriers + per-group double-buffered cp.async, smem
// reduction per phase. Raises per-SM warps from 8 to 16 at unchanged 4x4
// register tiles (FFMA:LDS balance preserved).

#define CATS     32
#define SDIM     64
#define EMB      256
#define ODIM     512
#define XDIM     512
#define MT       16     // rows per tile
#define KC       16     // K-chunk
#define KCE      (KC * EMB)   // floats per chunk buffer (4096)
#define NTHREADS 512
#define B_MAX    2048

__device__ int g_perm[B_MAX];
__device__ int g_cat_start[CATS + 1];

// ---------------------------------------------------------------------------
// Kernel 1: bin rows by category.
// ---------------------------------------------------------------------------
__global__ void bin_kernel(const int* __restrict__ cat, int B) {
    __shared__ int cnt[CATS];
    __shared__ int st[CATS + 1];
    __shared__ int cur[CATS];
    int t = threadIdx.x;
    if (t < CATS) cnt[t] = 0;
    __syncthreads();
    for (int b = t; b < B; b += blockDim.x) atomicAdd(&cnt[cat[b]], 1);
    __syncthreads();
    if (t == 0) {
        int s = 0;
        for (int c = 0; c < CATS; c++) { st[c] = s; s += cnt[c]; }
        st[CATS] = s;
    }
    __syncthreads();
    if (t < CATS) cur[t] = st[t];
    __syncthreads();
    for (int b = t; b < B; b += blockDim.x) {
        int pos = atomicAdd(&cur[cat[b]], 1);
        g_perm[pos] = b;
    }
    if (t <= CATS) g_cat_start[t] = st[t];
}

// ---------------------------------------------------------------------------
// Group-split GEMM: this thread's group handles chunks first, first+2, ...
// acc[4 rows][4 cols] accumulates this group's K-partial sum.
// wb0/wb1: this group's private double buffers. barid: group-scoped barrier.
// ---------------------------------------------------------------------------
__device__ __forceinline__ void grp_bar(int barid) {
    asm volatile("bar.sync %0, %1;" :: "r"(barid), "r"(256) : "memory");
}

__device__ __forceinline__ void gemm_split(
    const float* __restrict__ A, int lda,
    const float* __restrict__ W, int K,
    float* wb0, float* wb1,
    int first, int barid,
    int gt, int r0, int c64, float4 acc[4])
{
    const float4* Wv = (const float4*)W;
    int nch = K / KC;            // always even (4 or 32)
    int count = nch >> 1;        // chunks this group owns
    // prologue: chunk `first` -> wb0
    {
        const float4* src = Wv + (size_t)first * (KCE / 4);
        uint32_t dst = (uint32_t)__cvta_generic_to_shared(wb0);
        #pragma unroll
        for (int i = gt; i < KCE / 4; i += 256)
            asm volatile("cp.async.cg.shared.global [%0], [%1], 16;"
                         :: "r"(dst + i * 16), "l"(src + i));
        asm volatile("cp.async.commit_group;");
    }
    for (int j = 0; j < count; j++) {
        int ch = first + 2 * j;
        float* wb = (j & 1) ? wb1 : wb0;
        if (j + 1 < count) {
            float* nb = (j & 1) ? wb0 : wb1;
            const float4* src = Wv + (size_t)(ch + 2) * (KCE / 4);
            uint32_t dst = (uint32_t)__cvta_generic_to_shared(nb);
            #pragma unroll
            for (int i = gt; i < KCE / 4; i += 256)
                asm volatile("cp.async.cg.shared.global [%0], [%1], 16;"
                             :: "r"(dst + i * 16), "l"(src + i));
            asm volatile("cp.async.commit_group;");
            asm volatile("cp.async.wait_group 1;");
        } else {
            asm volatile("cp.async.wait_group 0;");
        }
        grp_bar(barid);
        const float* A0 = A + (r0 + 0) * lda + ch * KC;
        const float* A1 = A0 + lda;
        const float* A2 = A1 + lda;
        const float* A3 = A2 + lda;
        const float4* Wrow = (const float4*)wb + c64;
        #pragma unroll
        for (int kk = 0; kk < KC; kk++) {
            float a0 = A0[kk], a1 = A1[kk], a2 = A2[kk], a3 = A3[kk];
            float4 w = Wrow[kk * 64];
            acc[0].x = fmaf(a0, w.x, acc[0].x);
            acc[0].y = fmaf(a0, w.y, acc[0].y);
            acc[0].z = fmaf(a0, w.z, acc[0].z);
            acc[0].w = fmaf(a0, w.w, acc[0].w);
            acc[1].x = fmaf(a1, w.x, acc[1].x);
            acc[1].y = fmaf(a1, w.y, acc[1].y);
            acc[1].z = fmaf(a1, w.z, acc[1].z);
            acc[1].w = fmaf(a1, w.w, acc[1].w);
            acc[2].x = fmaf(a2, w.x, acc[2].x);
            acc[2].y = fmaf(a2, w.y, acc[2].y);
            acc[2].z = fmaf(a2, w.z, acc[2].z);
            acc[2].w = fmaf(a2, w.w, acc[2].w);
            acc[3].x = fmaf(a3, w.x, acc[3].x);
            acc[3].y = fmaf(a3, w.y, acc[3].y);
            acc[3].z = fmaf(a3, w.z, acc[3].z);
            acc[3].w = fmaf(a3, w.w, acc[3].w);
        }
        grp_bar(barid);  // buffer wb will be overwritten at j+1's prefetch
    }
}

// ---------------------------------------------------------------------------
// Kernel 2: fused per (category, 16-row tile), 512 threads, K-parity split.
// smem (floats): s_s 1024 | o_s 8192 | x_s 8192 | w[4][4096] | red 4096
// total = 37888 floats = 151552 bytes.
// ---------------------------------------------------------------------------
#define SMEM_FLOATS (MT*SDIM + MT*ODIM + MT*XDIM + 4*KCE + MT*EMB)

__global__ __launch_bounds__(NTHREADS, 1)
void fused_kernel(const float* __restrict__ state,
                  const float* __restrict__ obs,
                  const float* __restrict__ obs_W,
                  const float* __restrict__ obs_b,
                  const float* __restrict__ state_W,
                  const float* __restrict__ state_b,
                  const float* __restrict__ l2_W,
                  const float* __restrict__ l2_b,
                  float* __restrict__ out)
{
    extern __shared__ float sm[];
    __shared__ int rows_sh[MT];
    float* s_s = sm;                        // 16 x 64
    float* o_s = s_s + MT * SDIM;           // 16 x 512
    float* x_s = o_s + MT * ODIM;           // 16 x 512 (concat target)
    float* wB  = x_s + MT * XDIM;           // 4 buffers of KCE
    float* red = wB + 4 * KCE;              // 16 x 256 reduction staging

    int g = blockIdx.x;
    int start = g_cat_start[g];
    int cnt   = g_cat_start[g + 1] - start;
    int ntiles = (cnt + MT - 1) >> 4;

    int t    = threadIdx.x;
    int grp  = t >> 8;              // 0 or 1
    int gt   = t & 255;
    int r0   = (gt >> 6) << 2;      // 0,4,8,12
    int c64  = gt & 63;             // float4 column index
    int barid = 1 + grp;
    float* wb0 = wB + grp * 2 * KCE;
    float* wb1 = wb0 + KCE;

    for (int tile = blockIdx.y; tile < ntiles; tile += gridDim.y) {
        __syncthreads();
        int base = start + tile * MT;
        if (t < MT) rows_sh[t] = (tile * MT + t < cnt) ? g_perm[base + t] : -1;
        __syncthreads();

        // gather state rows: 16x64 = 256 float4
        if (t < 256) {
            int r = t >> 4, c4 = t & 15;
            int row = rows_sh[r];
            float4 v = make_float4(0.f, 0.f, 0.f, 0.f);
            if (row >= 0) v = ((const float4*)state)[row * 16 + c4];
            ((float4*)s_s)[t] = v;
        }
        // gather obs rows: 16x512 = 2048 float4
        #pragma unroll
        for (int i = t; i < MT * 128; i += NTHREADS) {
            int r = i >> 7, c4 = i & 127;
            int row = rows_sh[r];
            float4 v = make_float4(0.f, 0.f, 0.f, 0.f);
            if (row >= 0) v = ((const float4*)obs)[row * 128 + c4];
            ((float4*)o_s)[i] = v;
        }
        __syncthreads();

        float4 acc[4];
        float4* redv = (float4*)red;

        // --- Phase A: state_emb = relu(state @ state_W[g] + state_b[g]) ---
        acc[0] = acc[1] = acc[2] = acc[3] = make_float4(0.f, 0.f, 0.f, 0.f);
        gemm_split(s_s, SDIM, state_W + (size_t)g * SDIM * EMB, SDIM,
                   wb0, wb1, grp, barid, gt, r0, c64, acc);
        __syncthreads();
        if (grp == 1) {
            #pragma unroll
            for (int ri = 0; ri < 4; ri++) redv[(r0 + ri) * 64 + c64] = acc[ri];
        }
        __syncthreads();
        if (grp == 0) {
            float4 bb = ((const float4*)(state_b + g * EMB))[c64];
            #pragma unroll
            for (int ri = 0; ri < 4; ri++) {
                float4 p = redv[(r0 + ri) * 64 + c64];
                float4 v;
                v.x = fmaxf(acc[ri].x + p.x + bb.x, 0.f);
                v.y = fmaxf(acc[ri].y + p.y + bb.y, 0.f);
                v.z = fmaxf(acc[ri].z + p.z + bb.z, 0.f);
                v.w = fmaxf(acc[ri].w + p.w + bb.w, 0.f);
                ((float4*)(x_s + (r0 + ri) * XDIM))[c64] = v;
            }
        }
        __syncthreads();   // red free; x_s cols [0,256) written

        // --- Phase B: obs_emb = obs @ obs_W + obs_b -> x cols [256,512) ---
        acc[0] = acc[1] = acc[2] = acc[3] = make_float4(0.f, 0.f, 0.f, 0.f);
        gemm_split(o_s, ODIM, obs_W, ODIM,
                   wb0, wb1, grp, barid, gt, r0, c64, acc);
        __syncthreads();
        if (grp == 1) {
            #pragma unroll
            for (int ri = 0; ri < 4; ri++) redv[(r0 + ri) * 64 + c64] = acc[ri];
        }
        __syncthreads();
        if (grp == 0) {
            float4 bb = ((const float4*)obs_b)[c64];
            #pragma unroll
            for (int ri = 0; ri < 4; ri++) {
                float4 p = redv[(r0 + ri) * 64 + c64];
                float4 v;
                v.x = acc[ri].x + p.x + bb.x;
                v.y = acc[ri].y + p.y + bb.y;
                v.z = acc[ri].z + p.z + bb.z;
                v.w = acc[ri].w + p.w + bb.w;
                ((float4*)(x_s + (r0 + ri) * XDIM + EMB))[c64] = v;
            }
        }
        __syncthreads();   // x_s complete

        // --- Phase C: out = x @ l2_W[g] + l2_b[g], scatter ---
        acc[0] = acc[1] = acc[2] = acc[3] = make_float4(0.f, 0.f, 0.f, 0.f);
        gemm_split(x_s, XDIM, l2_W + (size_t)g * XDIM * EMB, XDIM,
                   wb0, wb1, grp, barid, gt, r0, c64, acc);
        __syncthreads();
        if (grp == 1) {
            #pragma unroll
            for (int ri = 0; ri < 4; ri++) redv[(r0 + ri) * 64 + c64] = acc[ri];
        }
        __syncthreads();
        if (grp == 0) {
            float4 bb = ((const float4*)(l2_b + g * EMB))[c64];
            #pragma unroll
            for (int ri = 0; ri < 4; ri++) {
                int row = rows_sh[r0 + ri];
                if (row >= 0) {
                    float4 p = redv[(r0 + ri) * 64 + c64];
                    float4 v;
                    v.x = acc[ri].x + p.x + bb.x;
                    v.y = acc[ri].y + p.y + bb.y;
                    v.z = acc[ri].z + p.z + bb.z;
                    v.w = acc[ri].w + p.w + bb.w;
                    ((float4*)(out + (size_t)row * EMB))[c64] = v;
                }
            }
        }
    }
}

// ---------------------------------------------------------------------------
extern "C" void kernel_launch(void* const* d_in, const int* in_sizes, int n_in,
                              void* d_out, int out_size) {
    const float* state   = (const float*)d_in[0];
    const float* obs     = (const float*)d_in[1];
    const int*   cat_ids = (const int*)  d_in[2];
    const float* obs_W   = (const float*)d_in[3];
    const float* obs_b   = (const float*)d_in[4];
    const float* state_W = (const float*)d_in[5];
    const float* state_b = (const float*)d_in[6];
    const float* l2_W    = (const float*)d_in[7];
    const float* l2_b    = (const float*)d_in[8];
    float* out = (float*)d_out;

    int B = in_sizes[2];

    size_t smem_bytes = SMEM_FLOATS * sizeof(float);  // 151552
    cudaFuncSetAttribute(fused_kernel,
                         cudaFuncAttributeMaxDynamicSharedMemorySize,
                         (int)smem_bytes);

    bin_kernel<<<1, 256>>>(cat_ids, B);

    dim3 grid(CATS, 8);
    fused_kernel<<<grid, NTHREADS, smem_bytes>>>(
        state, obs, obs_W, obs_b, state_W, state_b, l2_W, l2_b, out);
}

// round 4
// speedup vs baseline: 1.1237x; 1.0856x over previous
#include <cuda_runtime.h>
#include <cstdint>

// StateObsMLP: B=2048 rows, C=32 categories.
//   obs_emb  = obs(512)   @ obs_W(512x256)        + obs_b
//   state_emb= relu(state(64) @ state_W[c](64x256) + state_b[c])
//   out      = concat(state_emb, obs_emb)(512) @ l2_W[c](512x256) + l2_b[c]
//
// R3: 512-thread CTAs with K-parity split (group0=even K-chunks, group1=odd),
// group-scoped named barriers + per-group double-buffered cp.async, smem
// reduction per phase. Raises per-SM warps from 8 to 16 at unchanged 4x4
// register tiles (FFMA:LDS balance preserved).

#define CATS     32
#define SDIM     64
#define EMB      256
#define ODIM     512
#define XDIM     512
#define MT       16     // rows per tile
#define KC       16     // K-chunk
#define KCE      (KC * EMB)   // floats per chunk buffer (4096)
#define NTHREADS 512
#define B_MAX    2048

__device__ int g_perm[B_MAX];
__device__ int g_cat_start[CATS + 1];

// ---------------------------------------------------------------------------
// Kernel 1: bin rows by category.
// ---------------------------------------------------------------------------
__global__ void bin_kernel(const int* __restrict__ cat, int B) {
    __shared__ int cnt[CATS];
    __shared__ int st[CATS + 1];
    __shared__ int cur[CATS];
    int t = threadIdx.x;
    if (t < CATS) cnt[t] = 0;
    __syncthreads();
    for (int b = t; b < B; b += blockDim.x) atomicAdd(&cnt[cat[b]], 1);
    __syncthreads();
    if (t == 0) {
        int s = 0;
        for (int c = 0; c < CATS; c++) { st[c] = s; s += cnt[c]; }
        st[CATS] = s;
    }
    __syncthreads();
    if (t < CATS) cur[t] = st[t];
    __syncthreads();
    for (int b = t; b < B; b += blockDim.x) {
        int pos = atomicAdd(&cur[cat[b]], 1);
        g_perm[pos] = b;
    }
    if (t <= CATS) g_cat_start[t] = st[t];
}

// ---------------------------------------------------------------------------
// Group-split GEMM: this thread's group handles chunks first, first+2, ...
// acc[4 rows][4 cols] accumulates this group's K-partial sum.
// wb0/wb1: this group's private double buffers. barid: group-scoped barrier.
// ---------------------------------------------------------------------------
__device__ __forceinline__ void grp_bar(int barid) {
    asm volatile("bar.sync %0, %1;" :: "r"(barid), "r"(256) : "memory");
}

__device__ __forceinline__ void gemm_split(
    const float* __restrict__ A, int lda,
    const float* __restrict__ W, int K,
    float* wb0, float* wb1,
    int first, int barid,
    int gt, int r0, int c64, float4 acc[4])
{
    const float4* Wv = (const float4*)W;
    int nch = K / KC;            // always even (4 or 32)
    int count = nch >> 1;        // chunks this group owns
    // prologue: chunk `first` -> wb0
    {
        const float4* src = Wv + (size_t)first * (KCE / 4);
        uint32_t dst = (uint32_t)__cvta_generic_to_shared(wb0);
        #pragma unroll
        for (int i = gt; i < KCE / 4; i += 256)
            asm volatile("cp.async.cg.shared.global [%0], [%1], 16;"
                         :: "r"(dst + i * 16), "l"(src + i));
        asm volatile("cp.async.commit_group;");
    }
    for (int j = 0; j < count; j++) {
        int ch = first + 2 * j;
        float* wb = (j & 1) ? wb1 : wb0;
        if (j + 1 < count) {
            float* nb = (j & 1) ? wb0 : wb1;
            const float4* src = Wv + (size_t)(ch + 2) * (KCE / 4);
            uint32_t dst = (uint32_t)__cvta_generic_to_shared(nb);
            #pragma unroll
            for (int i = gt; i < KCE / 4; i += 256)
                asm volatile("cp.async.cg.shared.global [%0], [%1], 16;"
                             :: "r"(dst + i * 16), "l"(src + i));
            asm volatile("cp.async.commit_group;");
            asm volatile("cp.async.wait_group 1;");
        } else {
            asm volatile("cp.async.wait_group 0;");
        }
        grp_bar(barid);
        const float* A0 = A + (r0 + 0) * lda + ch * KC;
        const float* A1 = A0 + lda;
        const float* A2 = A1 + lda;
        const float* A3 = A2 + lda;
        const float4* Wrow = (const float4*)wb + c64;
        #pragma unroll
        for (int kk = 0; kk < KC; kk++) {
            float a0 = A0[kk], a1 = A1[kk], a2 = A2[kk], a3 = A3[kk];
            float4 w = Wrow[kk * 64];
            acc[0].x = fmaf(a0, w.x, acc[0].x);
            acc[0].y = fmaf(a0, w.y, acc[0].y);
            acc[0].z = fmaf(a0, w.z, acc[0].z);
            acc[0].w = fmaf(a0, w.w, acc[0].w);
            acc[1].x = fmaf(a1, w.x, acc[1].x);
            acc[1].y = fmaf(a1, w.y, acc[1].y);
            acc[1].z = fmaf(a1, w.z, acc[1].z);
            acc[1].w = fmaf(a1, w.w, acc[1].w);
            acc[2].x = fmaf(a2, w.x, acc[2].x);
            acc[2].y = fmaf(a2, w.y, acc[2].y);
            acc[2].z = fmaf(a2, w.z, acc[2].z);
            acc[2].w = fmaf(a2, w.w, acc[2].w);
            acc[3].x = fmaf(a3, w.x, acc[3].x);
            acc[3].y = fmaf(a3, w.y, acc[3].y);
            acc[3].z = fmaf(a3, w.z, acc[3].z);
            acc[3].w = fmaf(a3, w.w, acc[3].w);
        }
        grp_bar(barid);  // buffer wb will be overwritten at j+1's prefetch
    }
}

// ---------------------------------------------------------------------------
// Kernel 2: fused per (category, 16-row tile), 512 threads, K-parity split.
// smem (floats): s_s 1024 | o_s 8192 | x_s 8192 | w[4][4096] | red 4096
// total = 37888 floats = 151552 bytes.
// ---------------------------------------------------------------------------
#define SMEM_FLOATS (MT*SDIM + MT*ODIM + MT*XDIM + 4*KCE + MT*EMB)

__global__ __launch_bounds__(NTHREADS, 1)
void fused_kernel(const float* __restrict__ state,
                  const float* __restrict__ obs,
                  const float* __restrict__ obs_W,
                  const float* __restrict__ obs_b,
                  const float* __restrict__ state_W,
                  const float* __restrict__ state_b,
                  const float* __restrict__ l2_W,
                  const float* __restrict__ l2_b,
                  float* __restrict__ out)
{
    extern __shared__ float sm[];
    __shared__ int rows_sh[MT];
    float* s_s = sm;                        // 16 x 64
    float* o_s = s_s + MT * SDIM;           // 16 x 512
    float* x_s = o_s + MT * ODIM;           // 16 x 512 (concat target)
    float* wB  = x_s + MT * XDIM;           // 4 buffers of KCE
    float* red = wB + 4 * KCE;              // 16 x 256 reduction staging

    int g = blockIdx.x;
    int start = g_cat_start[g];
    int cnt   = g_cat_start[g + 1] - start;
    int ntiles = (cnt + MT - 1) >> 4;

    int t    = threadIdx.x;
    int grp  = t >> 8;              // 0 or 1
    int gt   = t & 255;
    int r0   = (gt >> 6) << 2;      // 0,4,8,12
    int c64  = gt & 63;             // float4 column index
    int barid = 1 + grp;
    float* wb0 = wB + grp * 2 * KCE;
    float* wb1 = wb0 + KCE;

    for (int tile = blockIdx.y; tile < ntiles; tile += gridDim.y) {
        __syncthreads();
        int base = start + tile * MT;
        if (t < MT) rows_sh[t] = (tile * MT + t < cnt) ? g_perm[base + t] : -1;
        __syncthreads();

        // gather state rows: 16x64 = 256 float4
        if (t < 256) {
            int r = t >> 4, c4 = t & 15;
            int row = rows_sh[r];
            float4 v = make_float4(0.f, 0.f, 0.f, 0.f);
            if (row >= 0) v = ((const float4*)state)[row * 16 + c4];
            ((float4*)s_s)[t] = v;
        }
        // gather obs rows: 16x512 = 2048 float4
        #pragma unroll
        for (int i = t; i < MT * 128; i += NTHREADS) {
            int r = i >> 7, c4 = i & 127;
            int row = rows_sh[r];
            float4 v = make_float4(0.f, 0.f, 0.f, 0.f);
            if (row >= 0) v = ((const float4*)obs)[row * 128 + c4];
            ((float4*)o_s)[i] = v;
        }
        __syncthreads();

        float4 acc[4];
        float4* redv = (float4*)red;

        // --- Phase A: state_emb = relu(state @ state_W[g] + state_b[g]) ---
        acc[0] = acc[1] = acc[2] = acc[3] = make_float4(0.f, 0.f, 0.f, 0.f);
        gemm_split(s_s, SDIM, state_W + (size_t)g * SDIM * EMB, SDIM,
                   wb0, wb1, grp, barid, gt, r0, c64, acc);
        __syncthreads();
        if (grp == 1) {
            #pragma unroll
            for (int ri = 0; ri < 4; ri++) redv[(r0 + ri) * 64 + c64] = acc[ri];
        }
        __syncthreads();
        if (grp == 0) {
            float4 bb = ((const float4*)(state_b + g * EMB))[c64];
            #pragma unroll
            for (int ri = 0; ri < 4; ri++) {
                float4 p = redv[(r0 + ri) * 64 + c64];
                float4 v;
                v.x = fmaxf(acc[ri].x + p.x + bb.x, 0.f);
                v.y = fmaxf(acc[ri].y + p.y + bb.y, 0.f);
                v.z = fmaxf(acc[ri].z + p.z + bb.z, 0.f);
                v.w = fmaxf(acc[ri].w + p.w + bb.w, 0.f);
                ((float4*)(x_s + (r0 + ri) * XDIM))[c64] = v;
            }
        }
        __syncthreads();   // red free; x_s cols [0,256) written

        // --- Phase B: obs_emb = obs @ obs_W + obs_b -> x cols [256,512) ---
        acc[0] = acc[1] = acc[2] = acc[3] = make_float4(0.f, 0.f, 0.f, 0.f);
        gemm_split(o_s, ODIM, obs_W, ODIM,
                   wb0, wb1, grp, barid, gt, r0, c64, acc);
        __syncthreads();
        if (grp == 1) {
            #pragma unroll
            for (int ri = 0; ri < 4; ri++) redv[(r0 + ri) * 64 + c64] = acc[ri];
        }
        __syncthreads();
        if (grp == 0) {
            float4 bb = ((const float4*)obs_b)[c64];
            #pragma unroll
            for (int ri = 0; ri < 4; ri++) {
                float4 p = redv[(r0 + ri) * 64 + c64];
                float4 v;
                v.x = acc[ri].x + p.x + bb.x;
                v.y = acc[ri].y + p.y + bb.y;
                v.z = acc[ri].z + p.z + bb.z;
                v.w = acc[ri].w + p.w + bb.w;
                ((float4*)(x_s + (r0 + ri) * XDIM + EMB))[c64] = v;
            }
        }
        __syncthreads();   // x_s complete

        // --- Phase C: out = x @ l2_W[g] + l2_b[g], scatter ---
        acc[0] = acc[1] = acc[2] = acc[3] = make_float4(0.f, 0.f, 0.f, 0.f);
        gemm_split(x_s, XDIM, l2_W + (size_t)g * XDIM * EMB, XDIM,
                   wb0, wb1, grp, barid, gt, r0, c64, acc);
        __syncthreads();
        if (grp == 1) {
            #pragma unroll
            for (int ri = 0; ri < 4; ri++) redv[(r0 + ri) * 64 + c64] = acc[ri];
        }
        __syncthreads();
        if (grp == 0) {
            float4 bb = ((const float4*)(l2_b + g * EMB))[c64];
            #pragma unroll
            for (int ri = 0; ri < 4; ri++) {
                int row = rows_sh[r0 + ri];
                if (row >= 0) {
                    float4 p = redv[(r0 + ri) * 64 + c64];
                    float4 v;
                    v.x = acc[ri].x + p.x + bb.x;
                    v.y = acc[ri].y + p.y + bb.y;
                    v.z = acc[ri].z + p.z + bb.z;
                    v.w = acc[ri].w + p.w + bb.w;
                    ((float4*)(out + (size_t)row * EMB))[c64] = v;
                }
            }
        }
    }
}

// ---------------------------------------------------------------------------
extern "C" void kernel_launch(void* const* d_in, const int* in_sizes, int n_in,
                              void* d_out, int out_size) {
    const float* state   = (const float*)d_in[0];
    const float* obs     = (const float*)d_in[1];
    const int*   cat_ids = (const int*)  d_in[2];
    const float* obs_W   = (const float*)d_in[3];
    const float* obs_b   = (const float*)d_in[4];
    const float* state_W = (const float*)d_in[5];
    const float* state_b = (const float*)d_in[6];
    const float* l2_W    = (const float*)d_in[7];
    const float* l2_b    = (const float*)d_in[8];
    float* out = (float*)d_out;

    int B = in_sizes[2];

    size_t smem_bytes = SMEM_FLOATS * sizeof(float);  // 151552
    cudaFuncSetAttribute(fused_kernel,
                         cudaFuncAttributeMaxDynamicSharedMemorySize,
                         (int)smem_bytes);

    bin_kernel<<<1, 256>>>(cat_ids, B);

    dim3 grid(CATS, 8);
    fused_kernel<<<grid, NTHREADS, smem_bytes>>>(
        state, obs, obs_W, obs_b, state_W, state_b, l2_W, l2_b, out);
}

// round 5
// speedup vs baseline: 1.1298x; 1.0054x over previous
#include <cuda_runtime.h>
#include <cstdint>

// StateObsMLP: B=2048 rows, C=32 categories.
//   obs_emb  = obs(512)   @ obs_W(512x256)        + obs_b
//   state_emb= relu(state(64) @ state_W[c](64x256) + state_b[c])
//   out      = concat(state_emb, obs_emb)(512) @ l2_W[c](512x256) + l2_b[c]
//
// R3: 512-thread CTAs with K-parity split (group0=even K-chunks, group1=odd),
// group-scoped named barriers + per-group double-buffered cp.async, smem
// reduction per phase. Raises per-SM warps from 8 to 16 at unchanged 4x4
// register tiles (FFMA:LDS balance preserved).

#define CATS     32
#define SDIM     64
#define EMB      256
#define ODIM     512
#define XDIM     512
#define MT       16     // rows per tile
#define KC       16     // K-chunk
#define KCE      (KC * EMB)   // floats per chunk buffer (4096)
#define NTHREADS 512
#define B_MAX    2048

__device__ int g_perm[B_MAX];
__device__ int g_cat_start[CATS + 1];

// ---------------------------------------------------------------------------
// Kernel 1: bin rows by category.
// ---------------------------------------------------------------------------
__global__ void bin_kernel(const int* __restrict__ cat, int B) {
    __shared__ int cnt[CATS];
    __shared__ int st[CATS + 1];
    __shared__ int cur[CATS];
    int t = threadIdx.x;
    if (t < CATS) cnt[t] = 0;
    __syncthreads();
    for (int b = t; b < B; b += blockDim.x) atomicAdd(&cnt[cat[b]], 1);
    __syncthreads();
    if (t == 0) {
        int s = 0;
        for (int c = 0; c < CATS; c++) { st[c] = s; s += cnt[c]; }
        st[CATS] = s;
    }
    __syncthreads();
    if (t < CATS) cur[t] = st[t];
    __syncthreads();
    for (int b = t; b < B; b += blockDim.x) {
        int pos = atomicAdd(&cur[cat[b]], 1);
        g_perm[pos] = b;
    }
    if (t <= CATS) g_cat_start[t] = st[t];
}

// ---------------------------------------------------------------------------
// Group-split GEMM: this thread's group handles chunks first, first+2, ...
// acc[4 rows][4 cols] accumulates this group's K-partial sum.
// wb0/wb1: this group's private double buffers. barid: group-scoped barrier.
// ---------------------------------------------------------------------------
__device__ __forceinline__ void grp_bar(int barid) {
    asm volatile("bar.sync %0, %1;" :: "r"(barid), "r"(256) : "memory");
}

__device__ __forceinline__ void gemm_split(
    const float* __restrict__ A, int lda,
    const float* __restrict__ W, int K,
    float* wb0, float* wb1,
    int first, int barid,
    int gt, int r0, int c64, float4 acc[4])
{
    const float4* Wv = (const float4*)W;
    int nch = K / KC;            // always even (4 or 32)
    int count = nch >> 1;        // chunks this group owns
    // prologue: chunk `first` -> wb0
    {
        const float4* src = Wv + (size_t)first * (KCE / 4);
        uint32_t dst = (uint32_t)__cvta_generic_to_shared(wb0);
        #pragma unroll
        for (int i = gt; i < KCE / 4; i += 256)
            asm volatile("cp.async.cg.shared.global [%0], [%1], 16;"
                         :: "r"(dst + i * 16), "l"(src + i));
        asm volatile("cp.async.commit_group;");
    }
    for (int j = 0; j < count; j++) {
        int ch = first + 2 * j;
        float* wb = (j & 1) ? wb1 : wb0;
        if (j + 1 < count) {
            float* nb = (j & 1) ? wb0 : wb1;
            const float4* src = Wv + (size_t)(ch + 2) * (KCE / 4);
            uint32_t dst = (uint32_t)__cvta_generic_to_shared(nb);
            #pragma unroll
            for (int i = gt; i < KCE / 4; i += 256)
                asm volatile("cp.async.cg.shared.global [%0], [%1], 16;"
                             :: "r"(dst + i * 16), "l"(src + i));
            asm volatile("cp.async.commit_group;");
            asm volatile("cp.async.wait_group 1;");
        } else {
            asm volatile("cp.async.wait_group 0;");
        }
        grp_bar(barid);
        const float* A0 = A + (r0 + 0) * lda + ch * KC;
        const float* A1 = A0 + lda;
        const float* A2 = A1 + lda;
        const float* A3 = A2 + lda;
        const float4* Wrow = (const float4*)wb + c64;
        #pragma unroll
        for (int kk = 0; kk < KC; kk++) {
            float a0 = A0[kk], a1 = A1[kk], a2 = A2[kk], a3 = A3[kk];
            float4 w = Wrow[kk * 64];
            acc[0].x = fmaf(a0, w.x, acc[0].x);
            acc[0].y = fmaf(a0, w.y, acc[0].y);
            acc[0].z = fmaf(a0, w.z, acc[0].z);
            acc[0].w = fmaf(a0, w.w, acc[0].w);
            acc[1].x = fmaf(a1, w.x, acc[1].x);
            acc[1].y = fmaf(a1, w.y, acc[1].y);
            acc[1].z = fmaf(a1, w.z, acc[1].z);
            acc[1].w = fmaf(a1, w.w, acc[1].w);
            acc[2].x = fmaf(a2, w.x, acc[2].x);
            acc[2].y = fmaf(a2, w.y, acc[2].y);
            acc[2].z = fmaf(a2, w.z, acc[2].z);
            acc[2].w = fmaf(a2, w.w, acc[2].w);
            acc[3].x = fmaf(a3, w.x, acc[3].x);
            acc[3].y = fmaf(a3, w.y, acc[3].y);
            acc[3].z = fmaf(a3, w.z, acc[3].z);
            acc[3].w = fmaf(a3, w.w, acc[3].w);
        }
        grp_bar(barid);  // buffer wb will be overwritten at j+1's prefetch
    }
}

// ---------------------------------------------------------------------------
// Kernel 2: fused per (category, 16-row tile), 512 threads, K-parity split.
// smem (floats): s_s 1024 | o_s 8192 | x_s 8192 | w[4][4096] | red 4096
// total = 37888 floats = 151552 bytes.
// ---------------------------------------------------------------------------
#define SMEM_FLOATS (MT*SDIM + MT*ODIM + MT*XDIM + 4*KCE + MT*EMB)

__global__ __launch_bounds__(NTHREADS, 1)
void fused_kernel(const float* __restrict__ state,
                  const float* __restrict__ obs,
                  const float* __restrict__ obs_W,
                  const float* __restrict__ obs_b,
                  const float* __restrict__ state_W,
                  const float* __restrict__ state_b,
                  const float* __restrict__ l2_W,
                  const float* __restrict__ l2_b,
                  float* __restrict__ out)
{
    extern __shared__ float sm[];
    __shared__ int rows_sh[MT];
    float* s_s = sm;                        // 16 x 64
    float* o_s = s_s + MT * SDIM;           // 16 x 512
    float* x_s = o_s + MT * ODIM;           // 16 x 512 (concat target)
    float* wB  = x_s + MT * XDIM;           // 4 buffers of KCE
    float* red = wB + 4 * KCE;              // 16 x 256 reduction staging

    int g = blockIdx.x;
    int start = g_cat_start[g];
    int cnt   = g_cat_start[g + 1] - start;
    int ntiles = (cnt + MT - 1) >> 4;

    int t    = threadIdx.x;
    int grp  = t >> 8;              // 0 or 1
    int gt   = t & 255;
    int r0   = (gt >> 6) << 2;      // 0,4,8,12
    int c64  = gt & 63;             // float4 column index
    int barid = 1 + grp;
    float* wb0 = wB + grp * 2 * KCE;
    float* wb1 = wb0 + KCE;

    for (int tile = blockIdx.y; tile < ntiles; tile += gridDim.y) {
        __syncthreads();
        int base = start + tile * MT;
        if (t < MT) rows_sh[t] = (tile * MT + t < cnt) ? g_perm[base + t] : -1;
        __syncthreads();

        // gather state rows: 16x64 = 256 float4
        if (t < 256) {
            int r = t >> 4, c4 = t & 15;
            int row = rows_sh[r];
            float4 v = make_float4(0.f, 0.f, 0.f, 0.f);
            if (row >= 0) v = ((const float4*)state)[row * 16 + c4];
            ((float4*)s_s)[t] = v;
        }
        // gather obs rows: 16x512 = 2048 float4
        #pragma unroll
        for (int i = t; i < MT * 128; i += NTHREADS) {
            int r = i >> 7, c4 = i & 127;
            int row = rows_sh[r];
            float4 v = make_float4(0.f, 0.f, 0.f, 0.f);
            if (row >= 0) v = ((const float4*)obs)[row * 128 + c4];
            ((float4*)o_s)[i] = v;
        }
        __syncthreads();

        float4 acc[4];
        float4* redv = (float4*)red;

        // --- Phase A: state_emb = relu(state @ state_W[g] + state_b[g]) ---
        acc[0] = acc[1] = acc[2] = acc[3] = make_float4(0.f, 0.f, 0.f, 0.f);
        gemm_split(s_s, SDIM, state_W + (size_t)g * SDIM * EMB, SDIM,
                   wb0, wb1, grp, barid, gt, r0, c64, acc);
        __syncthreads();
        if (grp == 1) {
            #pragma unroll
            for (int ri = 0; ri < 4; ri++) redv[(r0 + ri) * 64 + c64] = acc[ri];
        }
        __syncthreads();
        if (grp == 0) {
            float4 bb = ((const float4*)(state_b + g * EMB))[c64];
            #pragma unroll
            for (int ri = 0; ri < 4; ri++) {
                float4 p = redv[(r0 + ri) * 64 + c64];
                float4 v;
                v.x = fmaxf(acc[ri].x + p.x + bb.x, 0.f);
                v.y = fmaxf(acc[ri].y + p.y + bb.y, 0.f);
                v.z = fmaxf(acc[ri].z + p.z + bb.z, 0.f);
                v.w = fmaxf(acc[ri].w + p.w + bb.w, 0.f);
                ((float4*)(x_s + (r0 + ri) * XDIM))[c64] = v;
            }
        }
        __syncthreads();   // red free; x_s cols [0,256) written

        // --- Phase B: obs_emb = obs @ obs_W + obs_b -> x cols [256,512) ---
        acc[0] = acc[1] = acc[2] = acc[3] = make_float4(0.f, 0.f, 0.f, 0.f);
        gemm_split(o_s, ODIM, obs_W, ODIM,
                   wb0, wb1, grp, barid, gt, r0, c64, acc);
        __syncthreads();
        if (grp == 1) {
            #pragma unroll
            for (int ri = 0; ri < 4; ri++) redv[(r0 + ri) * 64 + c64] = acc[ri];
        }
        __syncthreads();
        if (grp == 0) {
            float4 bb = ((const float4*)obs_b)[c64];
            #pragma unroll
            for (int ri = 0; ri < 4; ri++) {
                float4 p = redv[(r0 + ri) * 64 + c64];
                float4 v;
                v.x = acc[ri].x + p.x + bb.x;
                v.y = acc[ri].y + p.y + bb.y;
                v.z = acc[ri].z + p.z + bb.z;
                v.w = acc[ri].w + p.w + bb.w;
                ((float4*)(x_s + (r0 + ri) * XDIM + EMB))[c64] = v;
            }
        }
        __syncthreads();   // x_s complete

        // --- Phase C: out = x @ l2_W[g] + l2_b[g], scatter ---
        acc[0] = acc[1] = acc[2] = acc[3] = make_float4(0.f, 0.f, 0.f, 0.f);
        gemm_split(x_s, XDIM, l2_W + (size_t)g * XDIM * EMB, XDIM,
                   wb0, wb1, grp, barid, gt, r0, c64, acc);
        __syncthreads();
        if (grp == 1) {
            #pragma unroll
            for (int ri = 0; ri < 4; ri++) redv[(r0 + ri) * 64 + c64] = acc[ri];
        }
        __syncthreads();
        if (grp == 0) {
            float4 bb = ((const float4*)(l2_b + g * EMB))[c64];
            #pragma unroll
            for (int ri = 0; ri < 4; ri++) {
                int row = rows_sh[r0 + ri];
                if (row >= 0) {
                    float4 p = redv[(r0 + ri) * 64 + c64];
                    float4 v;
                    v.x = acc[ri].x + p.x + bb.x;
                    v.y = acc[ri].y + p.y + bb.y;
                    v.z = acc[ri].z + p.z + bb.z;
                    v.w = acc[ri].w + p.w + bb.w;
                    ((float4*)(out + (size_t)row * EMB))[c64] = v;
                }
            }
        }
    }
}

// ---------------------------------------------------------------------------
extern "C" void kernel_launch(void* const* d_in, const int* in_sizes, int n_in,
                              void* d_out, int out_size) {
    const float* state   = (const float*)d_in[0];
    const float* obs     = (const float*)d_in[1];
    const int*   cat_ids = (const int*)  d_in[2];
    const float* obs_W   = (const float*)d_in[3];
    const float* obs_b   = (const float*)d_in[4];
    const float* state_W = (const float*)d_in[5];
    const float* state_b = (const float*)d_in[6];
    const float* l2_W    = (const float*)d_in[7];
    const float* l2_b    = (const float*)d_in[8];
    float* out = (float*)d_out;

    int B = in_sizes[2];

    size_t smem_bytes = SMEM_FLOATS * sizeof(float);  // 151552
    cudaFuncSetAttribute(fused_kernel,
                         cudaFuncAttributeMaxDynamicSharedMemorySize,
                         (int)smem_bytes);

    bin_kernel<<<1, 256>>>(cat_ids, B);

    dim3 grid(CATS, 8);
    fused_kernel<<<grid, NTHREADS, smem_bytes>>>(
        state, obs, obs_W, obs_b, state_W, state_b, l2_W, l2_b, out);
}